// round 16
// baseline (speedup 1.0000x reference)
#include <cuda_runtime.h>
#include <math.h>

// Fused SNN spike layer (R16 = R14, cache hints removed, A/B loads interleaved).
//  Per warp: rows rA = 2*(global warp), rB = rA+1 (contiguous; row B at
//  compile-time +Q4 offsets from row A's base). ALL 6 LDG.128 issued
//  back-to-back, A/B interleaved (MLP=6), then sums -> bounds -> handle.
//  Counts are float sums (x in {0,1}); bound u <= sum_d M[d]*sum16[C-d]
//  (Hoelder, M[d] = max srm tap over chunk-lag range). Refractory <= 0 =>
//  unflagged rows never spike -> STG.128 zeros.
//  S2: flagged -> warp-parallel windowed live-recurrence overestimate;
//      Af*max < theta - 2e-3 => exact u < theta => row exactly zero.
//  S3: else lane 0 full exact scan (R1/R5 arithmetic; rel_err = 0 x10).

#define T_LEN    300
#define Q4       75
#define NTH      256
#define WPB      8
#define RPB      (WPB * 2)     // 16 rows per block
#define NCH16    19
#define PENDN    16
#define NDELTA   8
#define THETA    10.0f
#define MARGIN1  0.02f
#define MARGIN2  2e-3f

__global__ __launch_bounds__(NTH, 7)
void snn_r16_kernel(const float* __restrict__ x,
                    const float* __restrict__ srm,
                    const float* __restrict__ refk,
                    float* __restrict__ out,
                    int B, int Ksrm, int Kref)
{
    __shared__ float s_M[NDELTA];
    __shared__ float s_rt[PENDN];
    __shared__ unsigned int cntw[WPB][2][20];   // double-buffered sums/warp

    const int tid  = threadIdx.x;
    const int lane = tid & 31;
    const int w    = tid >> 5;

    if (tid < PENDN) {
        float v = 0.0f;
        if (tid + 1 < Kref) v = refk[tid + 1];
        s_rt[tid] = v;
    }
    if (tid < NDELTA) {
        int lo = 16 * tid - 15; if (lo < 0) lo = 0;
        int hi = 16 * tid + 15; if (hi > Ksrm - 1) hi = Ksrm - 1;
        float m = 0.0f;
        for (int k = lo; k <= hi; ++k) m = fmaxf(m, srm[k]);
        s_M[tid] = m;
    }
    __syncthreads();   // only block-wide sync

    const float4 z = make_float4(0.f, 0.f, 0.f, 0.f);
    const int rA = blockIdx.x * RPB + w * 2;
    const int rB = rA + 1;

    // single base pointer; row B at compile-time float4 offsets (+Q4 ...)
    const float4* xA4 = (const float4*)(x + (size_t)rA * T_LEN);

    // ---- all 6 loads back-to-back, A/B interleaved (MLP = 6) ----
    float4 a0 = z, a1 = z, a2 = z, b0 = z, b1 = z, b2 = z;
    const bool okA = (rA < B);
    const bool okB = (rB < B);
    if (okA) a0 = xA4[lane];
    if (okB) b0 = xA4[Q4 + lane];
    if (okA) a1 = xA4[32 + lane];
    if (okB) b1 = xA4[Q4 + 32 + lane];
    if (okA && lane < Q4 - 64) a2 = xA4[64 + lane];
    if (okB && lane < Q4 - 64) b2 = xA4[Q4 + 64 + lane];

    // ---- sums A/B -> slots 0/1 (x in {0,1}: sum == count) ----
    {
        unsigned char* ca = (unsigned char*)cntw[w][0];
        ca[lane]      = (unsigned char)(int)((a0.x + a0.y) + (a0.z + a0.w));
        ca[32 + lane] = (unsigned char)(int)((a1.x + a1.y) + (a1.z + a1.w));
        if (lane < Q4 - 64)
            ca[64 + lane] = (unsigned char)(int)((a2.x + a2.y) + (a2.z + a2.w));
        else if (lane < 16)
            ca[64 + lane] = 0;               // pad bytes 75..79
        unsigned char* cb = (unsigned char*)cntw[w][1];
        cb[lane]      = (unsigned char)(int)((b0.x + b0.y) + (b0.z + b0.w));
        cb[32 + lane] = (unsigned char)(int)((b1.x + b1.y) + (b1.z + b1.w));
        if (lane < Q4 - 64)
            cb[64 + lane] = (unsigned char)(int)((b2.x + b2.y) + (b2.z + b2.w));
        else if (lane < 16)
            cb[64 + lane] = 0;
        __syncwarp();
    }

    // ---- bounds A and B ----
    bool flagA, flagB;
    {
        float bsA = 0.0f, bsB = 0.0f;
        if (lane < NCH16) {
#pragma unroll
            for (int d = 0; d < NDELTA; ++d) {
                const int c = lane - d;
                if (c >= 0) {
                    const unsigned sa = __dp4a(cntw[w][0][c], 0x01010101u, 0u);
                    const unsigned sb = __dp4a(cntw[w][1][c], 0x01010101u, 0u);
                    bsA = fmaf(s_M[d], (float)sa, bsA);
                    bsB = fmaf(s_M[d], (float)sb, bsB);
                }
            }
        }
        const bool act = (lane < NCH16);
        flagA = __any_sync(0xFFFFFFFFu, act && (bsA >= THETA - MARGIN1));
        flagB = __any_sync(0xFFFFFFFFu, act && (bsB >= THETA - MARGIN1));
    }

    // ---- per-row handler (zero / S2 / S3), identical math to R9b/R14 ----
    auto handle_row = [&](int r, bool flagged) {
        if (r >= B) return;
        float4* or4 = (float4*)(out + (size_t)r * T_LEN);
        if (!flagged) {
            or4[lane] = z;
            or4[32 + lane] = z;
            if (lane < Q4 - 64) or4[64 + lane] = z;
            return;
        }
        // rare path: recurrence constants (identical derivation to R1/R5)
        const double f1d = (double)srm[1];
        const double f2d = (double)srm[2];
        const double ddd = f2d / (2.0 * f1d);
        const double Add = f1d / ddd;
        const float dcy = (float)ddd;
        const float Af  = (float)Add;
        const float* xr = x + (size_t)r * T_LEN;

        // S2: warp-parallel windowed overestimate
        float mx = -1e30f;
        if (lane < 30) {
            const int tstart = lane * 10;
            int t0 = tstart - (Ksrm - 1); if (t0 < 0) t0 = 0;
            float s1 = 0.0f, s2 = 0.0f;
            for (int t = t0; t < tstart; ++t) {
                s2 = dcy * (s2 + s1);
                s1 = fmaf(dcy, s1, xr[t]);
            }
#pragma unroll
            for (int t = tstart; t < tstart + 10; ++t) {
                s2 = dcy * (s2 + s1);
                s1 = fmaf(dcy, s1, xr[t]);
                mx = fmaxf(mx, s2);
            }
        }
#pragma unroll
        for (int o = 16; o; o >>= 1)
            mx = fmaxf(mx, __shfl_xor_sync(0xFFFFFFFFu, mx, o));

        if (Af * mx < THETA - MARGIN2) {
            or4[lane] = z;
            or4[32 + lane] = z;
            if (lane < Q4 - 64) or4[64 + lane] = z;
        } else if (lane == 0) {
            // S3: full exact scan
            const float dK  = exp2f((float)Ksrm * log2f(dcy));
            const float C2c = Af * dK;
            const float C1c = Af * (float)Ksrm * dK;
            float* orow = out + (size_t)r * T_LEN;

            float s1 = 0.0f, s2 = 0.0f, s1d = 0.0f, s2d = 0.0f;
            float p[PENDN];
#pragma unroll
            for (int j = 0; j < PENDN; ++j) p[j] = 0.0f;

            for (int t = 0; t < T_LEN; ++t) {
                const float xv = xr[t];
                const int j2 = t - Ksrm;
                const float xd = (j2 >= 0) ? xr[j2] : 0.0f;

                s2  = dcy * (s2 + s1);
                s1  = fmaf(dcy, s1, xv);
                s2d = dcy * (s2d + s1d);
                s1d = fmaf(dcy, s1d, xd);

                const float u    = fmaf(-C1c, s1d, fmaf(-C2c, s2d, Af * s2));
                const float ueff = u + p[0];
                const float s    = (ueff >= THETA) ? 1.0f : 0.0f;

#pragma unroll
                for (int j = 0; j < PENDN - 1; ++j)
                    p[j] = fmaf(s, s_rt[j], p[j + 1]);
                p[PENDN - 1] = s * s_rt[PENDN - 1];

                orow[t] = s;
            }
        }
    };

    handle_row(rA, flagA);
    handle_row(rB, flagB);
}

extern "C" void kernel_launch(void* const* d_in, const int* in_sizes, int n_in,
                              void* d_out, int out_size)
{
    const float* x    = (const float*)d_in[0];
    const float* srm  = (const float*)d_in[1];
    const float* refk = (const float*)d_in[2];
    float* out        = (float*)d_out;

    const int total = in_sizes[0];
    const int B     = total / T_LEN;
    const int Ksrm  = in_sizes[1];
    const int Kref  = in_sizes[2];

    const int grid = (B + RPB - 1) / RPB;
    snn_r16_kernel<<<grid, NTH>>>(x, srm, refk, out, B, Ksrm, Kref);
}

// round 17
// speedup vs baseline: 1.0713x; 1.0713x over previous
#include <cuda_runtime.h>
#include <math.h>

// Fused SNN spike layer — FINAL (== R14, best bench 29.47us; kernel-level
// identical to R16 within noise; rel_err = 0 in 10 consecutive rounds).
//
// Algorithm (115us baseline -> ~29us, ~3.9x, ~1us from mixed-stream floor):
//  * Per warp: rows rA = 2*(global warp), rB = rA+1 (contiguous; row B at
//    compile-time +Q4 offsets from row A's base pointer). All 6 LDG.128
//    issued back-to-back (MLP=6, .cs streaming).
//  * Counts as float sums (x in {0,1} exactly -> sum == nonzero count;
//    FADD on the near-idle fma pipe instead of FSETP/IADD chains).
//  * Stage-1 filter: rigorous Hoelder bound
//      u[t in chunk C] <= sum_d M[d] * sum16[C-d],
//    M[d] = max srm tap over the chunk-lag range (derived on device from
//    the actual srm kernel). Refractory kernel <= 0 => u_eff <= u, so
//    unflagged rows can NEVER spike -> coalesced STG.128 zero-fill.
//  * Stage-2 (flagged rows, ~1%): warp-parallel windowed live-recurrence
//    OVERestimate of the exact truncated PSP (fresh 2-state alpha-kernel
//    recurrence per 10-step window with <=K-1-step warmup; all dropped
//    terms nonnegative). Af*max < theta - 2e-3 => exact u < theta =>
//    output exactly zero.
//  * Stage-3 (max u >= theta; ~0 rows): exact sequential scan. Truncated
//    K-tap conv via live + K-delayed 2-state recurrences; refractory
//    pending buffer as fully-unrolled FMA shift register (s in {0,1} makes
//    fma(s,rt,p) bit-identical to p + s*rt).

#define T_LEN    300
#define Q4       75
#define NTH      256
#define WPB      8
#define RPB      (WPB * 2)     // 16 rows per block
#define NCH16    19
#define PENDN    16
#define NDELTA   8
#define THETA    10.0f
#define MARGIN1  0.02f
#define MARGIN2  2e-3f

__global__ __launch_bounds__(NTH, 7)
void snn_final_kernel(const float* __restrict__ x,
                      const float* __restrict__ srm,
                      const float* __restrict__ refk,
                      float* __restrict__ out,
                      int B, int Ksrm, int Kref)
{
    __shared__ float s_M[NDELTA];
    __shared__ float s_rt[PENDN];
    __shared__ unsigned int cntw[WPB][2][20];   // double-buffered sums/warp

    const int tid  = threadIdx.x;
    const int lane = tid & 31;
    const int w    = tid >> 5;

    if (tid < PENDN) {
        float v = 0.0f;
        if (tid + 1 < Kref) v = refk[tid + 1];
        s_rt[tid] = v;
    }
    if (tid < NDELTA) {
        int lo = 16 * tid - 15; if (lo < 0) lo = 0;
        int hi = 16 * tid + 15; if (hi > Ksrm - 1) hi = Ksrm - 1;
        float m = 0.0f;
        for (int k = lo; k <= hi; ++k) m = fmaxf(m, srm[k]);
        s_M[tid] = m;
    }
    __syncthreads();   // only block-wide sync

    const float4 z = make_float4(0.f, 0.f, 0.f, 0.f);
    const int rA = blockIdx.x * RPB + w * 2;
    const int rB = rA + 1;

    // single base pointer; row B at compile-time float4 offsets (+Q4 ...)
    const float4* xA4 = (const float4*)(x + (size_t)rA * T_LEN);

    // ---- all 6 loads back-to-back (MLP = 6, streaming) ----
    float4 a0 = z, a1 = z, a2 = z, b0 = z, b1 = z, b2 = z;
    if (rA < B) {
        a0 = __ldcs(xA4 + lane);
        a1 = __ldcs(xA4 + 32 + lane);
        if (lane < Q4 - 64) a2 = __ldcs(xA4 + 64 + lane);
    }
    if (rB < B) {
        b0 = __ldcs(xA4 + Q4 + lane);
        b1 = __ldcs(xA4 + Q4 + 32 + lane);
        if (lane < Q4 - 64) b2 = __ldcs(xA4 + Q4 + 64 + lane);
    }

    // ---- sums A/B -> slots 0/1 (x in {0,1}: sum == count) ----
    {
        unsigned char* ca = (unsigned char*)cntw[w][0];
        ca[lane]      = (unsigned char)(int)((a0.x + a0.y) + (a0.z + a0.w));
        ca[32 + lane] = (unsigned char)(int)((a1.x + a1.y) + (a1.z + a1.w));
        if (lane < Q4 - 64)
            ca[64 + lane] = (unsigned char)(int)((a2.x + a2.y) + (a2.z + a2.w));
        else if (lane < 16)
            ca[64 + lane] = 0;               // pad bytes 75..79
        unsigned char* cb = (unsigned char*)cntw[w][1];
        cb[lane]      = (unsigned char)(int)((b0.x + b0.y) + (b0.z + b0.w));
        cb[32 + lane] = (unsigned char)(int)((b1.x + b1.y) + (b1.z + b1.w));
        if (lane < Q4 - 64)
            cb[64 + lane] = (unsigned char)(int)((b2.x + b2.y) + (b2.z + b2.w));
        else if (lane < 16)
            cb[64 + lane] = 0;
        __syncwarp();
    }

    // ---- bounds A and B ----
    bool flagA, flagB;
    {
        float bsA = 0.0f, bsB = 0.0f;
        if (lane < NCH16) {
#pragma unroll
            for (int d = 0; d < NDELTA; ++d) {
                const int c = lane - d;
                if (c >= 0) {
                    const unsigned sa = __dp4a(cntw[w][0][c], 0x01010101u, 0u);
                    const unsigned sb = __dp4a(cntw[w][1][c], 0x01010101u, 0u);
                    bsA = fmaf(s_M[d], (float)sa, bsA);
                    bsB = fmaf(s_M[d], (float)sb, bsB);
                }
            }
        }
        const bool act = (lane < NCH16);
        flagA = __any_sync(0xFFFFFFFFu, act && (bsA >= THETA - MARGIN1));
        flagB = __any_sync(0xFFFFFFFFu, act && (bsB >= THETA - MARGIN1));
    }

    // ---- per-row handler (zero / S2 / S3) ----
    auto handle_row = [&](int r, bool flagged) {
        if (r >= B) return;
        float4* or4 = (float4*)(out + (size_t)r * T_LEN);
        if (!flagged) {
            __stcs(or4 + lane, z);
            __stcs(or4 + 32 + lane, z);
            if (lane < Q4 - 64) __stcs(or4 + 64 + lane, z);
            return;
        }
        // rare path: recurrence constants from srm taps
        // srm[k] = A*k*d^k => d = srm[2]/(2*srm[1]), A = srm[1]/d
        const double f1d = (double)srm[1];
        const double f2d = (double)srm[2];
        const double ddd = f2d / (2.0 * f1d);
        const double Add = f1d / ddd;
        const float dcy = (float)ddd;
        const float Af  = (float)Add;
        const float* xr = x + (size_t)r * T_LEN;

        // S2: warp-parallel windowed overestimate
        float mx = -1e30f;
        if (lane < 30) {
            const int tstart = lane * 10;
            int t0 = tstart - (Ksrm - 1); if (t0 < 0) t0 = 0;
            float s1 = 0.0f, s2 = 0.0f;
            for (int t = t0; t < tstart; ++t) {
                s2 = dcy * (s2 + s1);
                s1 = fmaf(dcy, s1, xr[t]);
            }
#pragma unroll
            for (int t = tstart; t < tstart + 10; ++t) {
                s2 = dcy * (s2 + s1);
                s1 = fmaf(dcy, s1, xr[t]);
                mx = fmaxf(mx, s2);
            }
        }
#pragma unroll
        for (int o = 16; o; o >>= 1)
            mx = fmaxf(mx, __shfl_xor_sync(0xFFFFFFFFu, mx, o));

        if (Af * mx < THETA - MARGIN2) {
            __stcs(or4 + lane, z);
            __stcs(or4 + 32 + lane, z);
            if (lane < Q4 - 64) __stcs(or4 + 64 + lane, z);
        } else if (lane == 0) {
            // S3: full exact scan
            const float dK  = exp2f((float)Ksrm * log2f(dcy));
            const float C2c = Af * dK;
            const float C1c = Af * (float)Ksrm * dK;
            float* orow = out + (size_t)r * T_LEN;

            float s1 = 0.0f, s2 = 0.0f, s1d = 0.0f, s2d = 0.0f;
            float p[PENDN];
#pragma unroll
            for (int j = 0; j < PENDN; ++j) p[j] = 0.0f;

            for (int t = 0; t < T_LEN; ++t) {
                const float xv = xr[t];
                const int j2 = t - Ksrm;
                const float xd = (j2 >= 0) ? xr[j2] : 0.0f;

                s2  = dcy * (s2 + s1);
                s1  = fmaf(dcy, s1, xv);
                s2d = dcy * (s2d + s1d);
                s1d = fmaf(dcy, s1d, xd);

                const float u    = fmaf(-C1c, s1d, fmaf(-C2c, s2d, Af * s2));
                const float ueff = u + p[0];
                const float s    = (ueff >= THETA) ? 1.0f : 0.0f;

#pragma unroll
                for (int j = 0; j < PENDN - 1; ++j)
                    p[j] = fmaf(s, s_rt[j], p[j + 1]);
                p[PENDN - 1] = s * s_rt[PENDN - 1];

                orow[t] = s;
            }
        }
    };

    handle_row(rA, flagA);
    handle_row(rB, flagB);
}

extern "C" void kernel_launch(void* const* d_in, const int* in_sizes, int n_in,
                              void* d_out, int out_size)
{
    const float* x    = (const float*)d_in[0];
    const float* srm  = (const float*)d_in[1];
    const float* refk = (const float*)d_in[2];
    float* out        = (float*)d_out;

    const int total = in_sizes[0];
    const int B     = total / T_LEN;
    const int Ksrm  = in_sizes[1];
    const int Kref  = in_sizes[2];

    const int grid = (B + RPB - 1) / RPB;
    snn_final_kernel<<<grid, NTH>>>(x, srm, refk, out, B, Ksrm, Kref);
}